// round 3
// baseline (speedup 1.0000x reference)
#include <cuda_runtime.h>
#include <cstdint>

// LinearKAN: out[b,o] = sum_i w[i,o]*silu(x[b,i]) + sum_{i,k} T_k(clip(tanh(x[b,i]))) * c[i,o,k] * w[i,o]
// B=64, I=512, O=512, K(basis)=8  ->  GEMM (64 x 4608) @ (4608 x 512), split-K.

#define BATCH   64
#define INF     512
#define OUTF    512
#define BASIS   8

#define NSPLIT  16      // K-splits over i (512/32)
#define ISPLIT  32      // i's per block
#define ISTAGE  8       // i's staged in smem at a time
#define OTILE   64      // o's per block  (grid.x = 512/64 = 8)
#define ISTRIDE 584     // 9*64 + 8 pad (breaks li-stride bank pattern)

__device__ float g_partial[NSPLIT * BATCH * OUTF];   // 2 MB scratch

__device__ __forceinline__ unsigned long long pack2(float lo, float hi) {
    unsigned long long r;
    asm("mov.b64 %0, {%1, %2};" : "=l"(r) : "f"(lo), "f"(hi));
    return r;
}
__device__ __forceinline__ void fma2(unsigned long long &acc, unsigned long long a,
                                     unsigned long long b) {
    asm("fma.rn.f32x2 %0, %1, %2, %3;" : "=l"(acc) : "l"(a), "l"(b), "l"(acc));
}
__device__ __forceinline__ void unpack2(unsigned long long v, float &lo, float &hi) {
    asm("mov.b64 {%0, %1}, %2;" : "=f"(lo), "=f"(hi) : "l"(v));
}

__global__ __launch_bounds__(256)
void kan_gemm(const float* __restrict__ x,
              const float* __restrict__ w,
              const float* __restrict__ c) {
    __shared__ float sd[ISTAGE * ISTRIDE];

    const int tid  = threadIdx.x;
    const int o0   = blockIdx.x * OTILE;     // o-tile base
    const int i0   = blockIdx.y * ISPLIT;    // K-split base
    const int ogrp = tid & 31;               // 32 o-pairs
    const int bgrp = tid >> 5;               // 8 b-groups (whole warp shares one)
    const int oa   = o0 + ogrp * 2;          // this thread's 2 adjacent o columns
    const int b0   = bgrp * 8;               // this thread's 8 b rows

    unsigned long long acc[2][4];
#pragma unroll
    for (int u = 0; u < 2; u++)
#pragma unroll
        for (int v = 0; v < 4; v++) acc[u][v] = 0ull;

    for (int stage = 0; stage < ISPLIT / ISTAGE; stage++) {
        const int ibase = i0 + stage * ISTAGE;

        __syncthreads();
        // ---- build basis slab: sd[li][j][b], j=0 silu, j=1..8 T_j ----
#pragma unroll
        for (int p = 0; p < 2; p++) {
            int idx = tid + p * 256;            // 0..511 = 8 i x 64 b
            int li  = idx & 7;
            int b   = idx >> 3;
            float xv  = x[b * INF + ibase + li];
            float sil = xv / (1.0f + __expf(-xv));
            float t   = tanhf(xv);
            t = fminf(fmaxf(t, -1.0f + 1e-6f), 1.0f - 1e-6f);
            float* sp = &sd[li * ISTRIDE + b];
            sp[0] = sil;
            float tm2 = t;                       // T1
            sp[64] = tm2;
            float tm1 = 2.0f * t * t - 1.0f;     // T2
            sp[128] = tm1;
#pragma unroll
            for (int k = 3; k <= BASIS; k++) {
                float tk = 2.0f * t * tm1 - tm2;
                sp[64 * k] = tk;
                tm2 = tm1; tm1 = tk;
            }
        }
        __syncthreads();

        // ---- GEMM over the staged 8 i's ----
#pragma unroll
        for (int li = 0; li < ISTAGE; li++) {
            const int i = ibase + li;
            // coefficients: j=0 -> w, j=1..8 -> c*w  (two adjacent o's = 16 contiguous c floats)
            float2 wv = *reinterpret_cast<const float2*>(w + (size_t)i * OUTF + oa);
            const float4* cp =
                reinterpret_cast<const float4*>(c + ((size_t)i * OUTF + oa) * BASIS);
            float4 q0 = cp[0], q1 = cp[1], q2 = cp[2], q3 = cp[3];

            unsigned long long cA[9], cB[9];
            cA[0] = pack2(wv.x, wv.x);
            cA[1] = pack2(q0.x * wv.x, q0.x * wv.x);
            cA[2] = pack2(q0.y * wv.x, q0.y * wv.x);
            cA[3] = pack2(q0.z * wv.x, q0.z * wv.x);
            cA[4] = pack2(q0.w * wv.x, q0.w * wv.x);
            cA[5] = pack2(q1.x * wv.x, q1.x * wv.x);
            cA[6] = pack2(q1.y * wv.x, q1.y * wv.x);
            cA[7] = pack2(q1.z * wv.x, q1.z * wv.x);
            cA[8] = pack2(q1.w * wv.x, q1.w * wv.x);
            cB[0] = pack2(wv.y, wv.y);
            cB[1] = pack2(q2.x * wv.y, q2.x * wv.y);
            cB[2] = pack2(q2.y * wv.y, q2.y * wv.y);
            cB[3] = pack2(q2.z * wv.y, q2.z * wv.y);
            cB[4] = pack2(q2.w * wv.y, q2.w * wv.y);
            cB[5] = pack2(q3.x * wv.y, q3.x * wv.y);
            cB[6] = pack2(q3.y * wv.y, q3.y * wv.y);
            cB[7] = pack2(q3.z * wv.y, q3.z * wv.y);
            cB[8] = pack2(q3.w * wv.y, q3.w * wv.y);

            const float* sp = &sd[li * ISTRIDE + b0];
#pragma unroll
            for (int j = 0; j < 9; j++) {
                // all 32 lanes of a warp read the same addresses -> broadcast, 0 conflicts
                unsigned long long d0 = *reinterpret_cast<const unsigned long long*>(sp + j * 64 + 0);
                unsigned long long d1 = *reinterpret_cast<const unsigned long long*>(sp + j * 64 + 2);
                unsigned long long d2 = *reinterpret_cast<const unsigned long long*>(sp + j * 64 + 4);
                unsigned long long d3 = *reinterpret_cast<const unsigned long long*>(sp + j * 64 + 6);
                fma2(acc[0][0], cA[j], d0);
                fma2(acc[0][1], cA[j], d1);
                fma2(acc[0][2], cA[j], d2);
                fma2(acc[0][3], cA[j], d3);
                fma2(acc[1][0], cB[j], d0);
                fma2(acc[1][1], cB[j], d1);
                fma2(acc[1][2], cB[j], d2);
                fma2(acc[1][3], cB[j], d3);
            }
        }
    }

    // ---- write partials: g_partial[split][b][o] ----
    float* pp = g_partial + (size_t)blockIdx.y * (BATCH * OUTF);
#pragma unroll
    for (int bb = 0; bb < 4; bb++) {
        float lo, hi;
        unpack2(acc[0][bb], lo, hi);
        pp[(b0 + 2 * bb    ) * OUTF + oa] = lo;
        pp[(b0 + 2 * bb + 1) * OUTF + oa] = hi;
        unpack2(acc[1][bb], lo, hi);
        pp[(b0 + 2 * bb    ) * OUTF + oa + 1] = lo;
        pp[(b0 + 2 * bb + 1) * OUTF + oa + 1] = hi;
    }
}

__global__ __launch_bounds__(512)
void kan_reduce(float* __restrict__ out) {
    int idx = blockIdx.x * blockDim.x + threadIdx.x;   // 0 .. 32767
    float s = 0.0f;
#pragma unroll
    for (int k = 0; k < NSPLIT; k++)
        s += g_partial[k * (BATCH * OUTF) + idx];
    out[idx] = s;
}

extern "C" void kernel_launch(void* const* d_in, const int* in_sizes, int n_in,
                              void* d_out, int out_size) {
    const float* x = (const float*)d_in[0];
    const float* w = (const float*)d_in[1];
    const float* c = (const float*)d_in[2];
    float* out = (float*)d_out;

    dim3 grid(OUTF / OTILE, NSPLIT);   // (8, 16)
    kan_gemm<<<grid, 256>>>(x, w, c);
    kan_reduce<<<(BATCH * OUTF) / 512, 512>>>(out);
}

// round 6
// speedup vs baseline: 1.0949x; 1.0949x over previous
#include <cuda_runtime.h>
#include <cstdint>

// LinearKAN: out[b,o] = sum_i w[i,o]*silu(x[b,i]) + sum_{i,k} T_k(clip(tanh(x[b,i])))*c[i,o,k]*w[i,o]
// == GEMM (64 x 4608) @ (4608 x 512), split-K over i, single fused kernel.

#define BATCH   64
#define INF     512
#define OUTF    512
#define BASIS   8

#define NSPLIT  32              // K-splits over i
#define ISPLIT  (INF / NSPLIT)  // 16 i's per block
#define ISTAGE  4               // i's staged in smem at a time
#define NSTAGE  (ISPLIT / ISTAGE)
#define OTILE   64              // grid.x = 8
#define NCOL    (OUTF / OTILE)

#define SB_STRIDE  584          // basis: 9*64 + 8 pad
#define SCW_STRIDE 576          // cw: 9*64

__device__ float g_partial[NSPLIT * BATCH * OUTF];   // 4 MB scratch
__device__ int   g_ctr[NCOL];                        // zero-init; self-resetting

__device__ __forceinline__ unsigned long long pack2(float lo, float hi) {
    unsigned long long r;
    asm("mov.b64 %0, {%1, %2};" : "=l"(r) : "f"(lo), "f"(hi));
    return r;
}
__device__ __forceinline__ void fma2(unsigned long long &acc, unsigned long long a,
                                     unsigned long long b) {
    asm("fma.rn.f32x2 %0, %1, %2, %3;" : "=l"(acc) : "l"(a), "l"(b), "l"(acc));
}
__device__ __forceinline__ void unpack2(unsigned long long v, float &lo, float &hi) {
    asm("mov.b64 {%0, %1}, %2;" : "=f"(lo), "=f"(hi) : "l"(v));
}

__global__ __launch_bounds__(256, 2)
void kan_fused(const float* __restrict__ x,
               const float* __restrict__ w,
               const float* __restrict__ c,
               float* __restrict__ out) {
    __shared__ __align__(16) float sb[ISTAGE * SB_STRIDE];    // basis [li][j][b]
    __shared__ __align__(16) float scw[ISTAGE * SCW_STRIDE];  // c*w   [li][j][o]
    __shared__ int s_last;

    const int tid  = threadIdx.x;
    const int o0   = blockIdx.x * OTILE;
    const int i0   = blockIdx.y * ISPLIT;
    const int ogrp = tid & 31;               // o-pair index within tile
    const int b0   = (tid >> 5) * 8;         // 8 b's per thread (warp shares b-group)

    // mapping A (basis build): one (li, b) per thread
    const int liA = tid & 3;
    const int bA  = tid >> 2;
    // mapping B (cw build): one (li, o) per thread
    const int liB = tid >> 6;
    const int oB  = tid & 63;

    // ---- prefetch stage 0 operands into registers ----
    float xr = x[bA * INF + i0 + liA];
    float wr = w[(size_t)(i0 + liB) * OUTF + o0 + oB];
    float4 q0, q1;
    {
        const float4* cp = reinterpret_cast<const float4*>(
            c + ((size_t)(i0 + liB) * OUTF + o0 + oB) * BASIS);
        q0 = cp[0]; q1 = cp[1];
    }

    unsigned long long acc[2][4];
#pragma unroll
    for (int u = 0; u < 2; u++)
#pragma unroll
        for (int v = 0; v < 4; v++) acc[u][v] = 0ull;

    for (int stage = 0; stage < NSTAGE; stage++) {
        __syncthreads();   // previous mainloop readers done

        // ---- build basis slab from registers ----
        {
            float sil = xr / (1.0f + __expf(-xr));
            float t   = tanhf(xr);
            t = fminf(fmaxf(t, -1.0f + 1e-6f), 1.0f - 1e-6f);
            float* sp = sb + liA * SB_STRIDE + bA;
            sp[0]   = sil;
            float tm2 = t;                      // T1
            sp[64]  = tm2;
            float tm1 = 2.0f * t * t - 1.0f;    // T2
            sp[128] = tm1;
#pragma unroll
            for (int k = 3; k <= BASIS; k++) {
                float tk = 2.0f * t * tm1 - tm2;
                sp[64 * k] = tk;
                tm2 = tm1; tm1 = tk;
            }
        }
        // ---- build cw slab from registers ----
        {
            float* cwp = scw + liB * SCW_STRIDE + oB;
            cwp[0]   = wr;
            cwp[64]  = q0.x * wr; cwp[128] = q0.y * wr;
            cwp[192] = q0.z * wr; cwp[256] = q0.w * wr;
            cwp[320] = q1.x * wr; cwp[384] = q1.y * wr;
            cwp[448] = q1.z * wr; cwp[512] = q1.w * wr;
        }
        __syncthreads();

        // ---- prefetch next stage (hidden under FMA mainloop) ----
        if (stage + 1 < NSTAGE) {
            const int ib = i0 + (stage + 1) * ISTAGE;
            xr = x[bA * INF + ib + liA];
            wr = w[(size_t)(ib + liB) * OUTF + o0 + oB];
            const float4* cp = reinterpret_cast<const float4*>(
                c + ((size_t)(ib + liB) * OUTF + o0 + oB) * BASIS);
            q0 = cp[0]; q1 = cp[1];
        }

        // ---- FMA mainloop over staged i's ----
#pragma unroll
        for (int li = 0; li < ISTAGE; li++) {
            const float* cwp = scw + li * SCW_STRIDE + 2 * ogrp;
            const float* sp  = sb  + li * SB_STRIDE  + b0;
#pragma unroll
            for (int j = 0; j < 9; j++) {
                float2 cw2 = *reinterpret_cast<const float2*>(cwp + j * 64);
                unsigned long long cA = pack2(cw2.x, cw2.x);
                unsigned long long cB = pack2(cw2.y, cw2.y);
                // all lanes same basis address -> broadcast, conflict-free
                unsigned long long d0 = *reinterpret_cast<const unsigned long long*>(sp + j * 64 + 0);
                unsigned long long d1 = *reinterpret_cast<const unsigned long long*>(sp + j * 64 + 2);
                unsigned long long d2 = *reinterpret_cast<const unsigned long long*>(sp + j * 64 + 4);
                unsigned long long d3 = *reinterpret_cast<const unsigned long long*>(sp + j * 64 + 6);
                fma2(acc[0][0], cA, d0);
                fma2(acc[0][1], cA, d1);
                fma2(acc[0][2], cA, d2);
                fma2(acc[0][3], cA, d3);
                fma2(acc[1][0], cB, d0);
                fma2(acc[1][1], cB, d1);
                fma2(acc[1][2], cB, d2);
                fma2(acc[1][3], cB, d3);
            }
        }
    }

    // ---- write partials: g_partial[split][b][o] ----
    float* pp = g_partial + (size_t)blockIdx.y * (BATCH * OUTF);
    const int oa = o0 + ogrp * 2;
#pragma unroll
    for (int bb = 0; bb < 4; bb++) {
        float lo, hi;
        unpack2(acc[0][bb], lo, hi);
        pp[(b0 + 2 * bb    ) * OUTF + oa] = lo;
        pp[(b0 + 2 * bb + 1) * OUTF + oa] = hi;
        unpack2(acc[1][bb], lo, hi);
        pp[(b0 + 2 * bb    ) * OUTF + oa + 1] = lo;
        pp[(b0 + 2 * bb + 1) * OUTF + oa + 1] = hi;
    }

    // ---- fused reduce: last block in this o-column sums the splits ----
    __threadfence();
    if (tid == 0)
        s_last = (atomicAdd(&g_ctr[blockIdx.x], 1) == NSPLIT - 1) ? 1 : 0;
    __syncthreads();
    if (s_last) {
        __threadfence();
        // 64 o x 64 b outputs = 1024 float4, 256 threads -> 4 quads each
#pragma unroll
        for (int rep = 0; rep < 4; rep++) {
            const int q  = tid + rep * 256;
            const int b  = q >> 4;
            const int oq = q & 15;
            const float* base = g_partial + (size_t)b * OUTF + o0 + oq * 4;
            float4 s = make_float4(0.f, 0.f, 0.f, 0.f);
#pragma unroll
            for (int sp2 = 0; sp2 < NSPLIT; sp2++) {
                float4 v = *reinterpret_cast<const float4*>(base + (size_t)sp2 * (BATCH * OUTF));
                s.x += v.x; s.y += v.y; s.z += v.z; s.w += v.w;
            }
            *reinterpret_cast<float4*>(out + (size_t)b * OUTF + o0 + oq * 4) = s;
        }
        __syncthreads();
        if (tid == 0) g_ctr[blockIdx.x] = 0;   // reset for next graph replay
    }
}

extern "C" void kernel_launch(void* const* d_in, const int* in_sizes, int n_in,
                              void* d_out, int out_size) {
    const float* x = (const float*)d_in[0];
    const float* w = (const float*)d_in[1];
    const float* c = (const float*)d_in[2];
    float* out = (float*)d_out;

    dim3 grid(NCOL, NSPLIT);   // (8, 32) = 256 blocks, all resident in one wave
    kan_fused<<<grid, 256>>>(x, w, c, out);
}